// round 1
// baseline (speedup 1.0000x reference)
#include <cuda_runtime.h>
#include <math.h>

// Problem constants
#define Bsz 16384
#define Dd  1024
#define Rr  64
#define Ee  4
#define Ll  3
#define ER  (Ee*Rr)        // 256

// Scratch (device globals — no allocation allowed)
__device__ float g_xl[Bsz * Dd];     // layer activation ping buffer
__device__ float g_t1[Bsz * ER];     // tanh(V xl)
__device__ float g_s [Bsz * ER];     // g_e * tanh(C t1)

#define BM 128
#define BN 128
#define BK 16

// ---------------------------------------------------------------------------
// GEMM1: t1[B,256] = tanh( xl[B,1024] @ Vl[256,1024]^T )   (NT, both K-contig)
// ---------------------------------------------------------------------------
__global__ __launch_bounds__(256)
void gemm1_tanh(const float* __restrict__ A,    // xl [M, 1024]
                const float* __restrict__ Bw)   // V layer [256, 1024]
{
    const int K = Dd;
    const int N = ER;
    __shared__ float As[BK][BM];
    __shared__ float Bs2[BK][BN];

    const int m0 = blockIdx.y * BM;
    const int n0 = blockIdx.x * BN;
    const int tid = threadIdx.x;
    const int tr = (tid >> 4) << 3;   // 0..120
    const int tc = (tid & 15) << 3;   // 0..120

    float acc[8][8];
    #pragma unroll
    for (int i = 0; i < 8; i++)
        #pragma unroll
        for (int j = 0; j < 8; j++) acc[i][j] = 0.f;

    for (int k0 = 0; k0 < K; k0 += BK) {
        #pragma unroll
        for (int p = 0; p < 2; p++) {
            int f  = tid + (p << 8);
            int r  = f >> 2;             // 0..127
            int c4 = (f & 3) << 2;       // 0,4,8,12
            float4 va = *(const float4*)(A  + (size_t)(m0 + r) * K + k0 + c4);
            As[c4+0][r] = va.x; As[c4+1][r] = va.y;
            As[c4+2][r] = va.z; As[c4+3][r] = va.w;
            float4 vb = *(const float4*)(Bw + (size_t)(n0 + r) * K + k0 + c4);
            Bs2[c4+0][r] = vb.x; Bs2[c4+1][r] = vb.y;
            Bs2[c4+2][r] = vb.z; Bs2[c4+3][r] = vb.w;
        }
        __syncthreads();
        #pragma unroll
        for (int k = 0; k < BK; k++) {
            float a[8], b[8];
            *(float4*)(a)     = *(const float4*)&As[k][tr];
            *(float4*)(a + 4) = *(const float4*)&As[k][tr + 4];
            *(float4*)(b)     = *(const float4*)&Bs2[k][tc];
            *(float4*)(b + 4) = *(const float4*)&Bs2[k][tc + 4];
            #pragma unroll
            for (int i = 0; i < 8; i++)
                #pragma unroll
                for (int j = 0; j < 8; j++)
                    acc[i][j] = fmaf(a[i], b[j], acc[i][j]);
        }
        __syncthreads();
    }

    #pragma unroll
    for (int i = 0; i < 8; i++) {
        const size_t row = (size_t)(m0 + tr + i);
        #pragma unroll
        for (int j4 = 0; j4 < 8; j4 += 4) {
            float4 v;
            v.x = tanhf(acc[i][j4 + 0]);
            v.y = tanhf(acc[i][j4 + 1]);
            v.z = tanhf(acc[i][j4 + 2]);
            v.w = tanhf(acc[i][j4 + 3]);
            *(float4*)(g_t1 + row * N + n0 + tc + j4) = v;
        }
    }
}

// ---------------------------------------------------------------------------
// gate_mix: per row b
//   logits_e = xl_b . gates_w_e ; g = softmax(logits)
//   s[b, e*64+r] = g_e * tanh( sum_s C[e,r,s] * t1[b, e*64+s] )
// One warp per row, 8 rows per block. C cached in padded smem.
// ---------------------------------------------------------------------------
__global__ __launch_bounds__(256)
void gate_mix(const float* __restrict__ xl,
              const float* __restrict__ Cw,   // layer C [E,R,R]
              const float* __restrict__ gw)   // gates_w [E, D]
{
    extern __shared__ float sm[];
    float* Cs  = sm;               // 4 * (64*65) floats, padded rows
    float* t1s = sm + 4 * 4160;    // 8 * 256 floats

    const int tid = threadIdx.x;
    // load C (padded: row stride 65 -> conflict-free strided reads)
    for (int idx = tid; idx < Ee * Rr * Rr; idx += 256) {
        int e = idx >> 12, rem = idx & 4095, r = rem >> 6, s = rem & 63;
        Cs[e * 4160 + r * 65 + s] = Cw[idx];
    }
    const int b0 = blockIdx.x << 3;
    for (int idx = tid; idx < 8 * 256; idx += 256) {
        int rl = idx >> 8, j = idx & 255;
        t1s[idx] = g_t1[(size_t)(b0 + rl) * ER + j];
    }
    __syncthreads();

    const int w = tid >> 5, lane = tid & 31;
    const int b = b0 + w;
    const float* xr = xl + (size_t)b * Dd;

    // gate logits: 4 dots of length 1024, coalesced
    float s0 = 0.f, s1 = 0.f, s2 = 0.f, s3 = 0.f;
    for (int d = lane; d < Dd; d += 32) {
        float xv = xr[d];
        s0 = fmaf(xv, gw[d],          s0);
        s1 = fmaf(xv, gw[Dd + d],     s1);
        s2 = fmaf(xv, gw[2 * Dd + d], s2);
        s3 = fmaf(xv, gw[3 * Dd + d], s3);
    }
    #pragma unroll
    for (int o = 16; o; o >>= 1) {
        s0 += __shfl_xor_sync(0xffffffffu, s0, o);
        s1 += __shfl_xor_sync(0xffffffffu, s1, o);
        s2 += __shfl_xor_sync(0xffffffffu, s2, o);
        s3 += __shfl_xor_sync(0xffffffffu, s3, o);
    }
    float mx = fmaxf(fmaxf(s0, s1), fmaxf(s2, s3));
    float e0 = expf(s0 - mx), e1 = expf(s1 - mx), e2 = expf(s2 - mx), e3 = expf(s3 - mx);
    float inv = 1.f / (e0 + e1 + e2 + e3);
    float gg[4] = { e0 * inv, e1 * inv, e2 * inv, e3 * inv };

    const float* t1r = t1s + w * ER;
    #pragma unroll
    for (int i = 0; i < 8; i++) {
        int j = (i << 5) + lane;                 // 0..255, lanes contiguous
        int e = j >> 6, r = j & 63;
        const float* cr = Cs + e * 4160 + r * 65;
        const float* tv = t1r + (e << 6);
        float sum = 0.f;
        #pragma unroll
        for (int s = 0; s < 64; s++) sum = fmaf(cr[s], tv[s], sum);
        g_s[(size_t)b * ER + j] = gg[e] * tanhf(sum);
    }
}

// ---------------------------------------------------------------------------
// GEMM2: out[B,1024] = xl + x0 * ( bias + s[B,256] @ W2 ),
//   W2[k=e*64+r][n=d] = U[e, d, r]  (addressed directly, no transpose:
//   BK=16 k-tiles never cross an expert's 64-wide contiguous r run)
// ---------------------------------------------------------------------------
__global__ __launch_bounds__(256)
void gemm2_combine(const float* __restrict__ Uw,     // layer U [E, D, R]
                   const float* __restrict__ xl_in,
                   const float* __restrict__ x0,
                   const float* __restrict__ bias,   // [D]
                   float* __restrict__ out)
{
    const int K = ER;       // 256
    const int N = Dd;       // 1024
    __shared__ float As[BK][BM];
    __shared__ float Bs2[BK][BN];

    const int m0 = blockIdx.y * BM;
    const int n0 = blockIdx.x * BN;
    const int tid = threadIdx.x;
    const int tr = (tid >> 4) << 3;
    const int tc = (tid & 15) << 3;

    float acc[8][8];
    #pragma unroll
    for (int i = 0; i < 8; i++)
        #pragma unroll
        for (int j = 0; j < 8; j++) acc[i][j] = 0.f;

    for (int k0 = 0; k0 < K; k0 += BK) {
        #pragma unroll
        for (int p = 0; p < 2; p++) {
            int f  = tid + (p << 8);
            int r  = f >> 2;
            int c4 = (f & 3) << 2;
            float4 va = *(const float4*)(g_s + (size_t)(m0 + r) * K + k0 + c4);
            As[c4+0][r] = va.x; As[c4+1][r] = va.y;
            As[c4+2][r] = va.z; As[c4+3][r] = va.w;
            int k  = k0 + c4;
            int e  = k >> 6;
            int rr = k & 63;
            float4 vb = *(const float4*)(Uw + (size_t)e * (Dd * Rr) + (size_t)(n0 + r) * Rr + rr);
            Bs2[c4+0][r] = vb.x; Bs2[c4+1][r] = vb.y;
            Bs2[c4+2][r] = vb.z; Bs2[c4+3][r] = vb.w;
        }
        __syncthreads();
        #pragma unroll
        for (int k = 0; k < BK; k++) {
            float a[8], b[8];
            *(float4*)(a)     = *(const float4*)&As[k][tr];
            *(float4*)(a + 4) = *(const float4*)&As[k][tr + 4];
            *(float4*)(b)     = *(const float4*)&Bs2[k][tc];
            *(float4*)(b + 4) = *(const float4*)&Bs2[k][tc + 4];
            #pragma unroll
            for (int i = 0; i < 8; i++)
                #pragma unroll
                for (int j = 0; j < 8; j++)
                    acc[i][j] = fmaf(a[i], b[j], acc[i][j]);
        }
        __syncthreads();
    }

    #pragma unroll
    for (int i = 0; i < 8; i++) {
        const size_t row = (size_t)(m0 + tr + i);
        #pragma unroll
        for (int j4 = 0; j4 < 8; j4 += 4) {
            const int col = n0 + tc + j4;
            const size_t idx = row * N + col;
            float4 xv  = *(const float4*)(xl_in + idx);
            float4 x0v = *(const float4*)(x0 + idx);
            float4 bv  = *(const float4*)(bias + col);
            float4 o;
            o.x = fmaf(x0v.x, bv.x + acc[i][j4 + 0], xv.x);
            o.y = fmaf(x0v.y, bv.y + acc[i][j4 + 1], xv.y);
            o.z = fmaf(x0v.z, bv.z + acc[i][j4 + 2], xv.z);
            o.w = fmaf(x0v.w, bv.w + acc[i][j4 + 3], xv.w);
            *(float4*)(out + idx) = o;
        }
    }
}

// ---------------------------------------------------------------------------
// Launch
// ---------------------------------------------------------------------------
extern "C" void kernel_launch(void* const* d_in, const int* in_sizes, int n_in,
                              void* d_out, int out_size)
{
    const float* x    = (const float*)d_in[0];   // [B, D]
    const float* U    = (const float*)d_in[1];   // [L, E, D, R]
    const float* V    = (const float*)d_in[2];   // [L, E, R, D]
    const float* C    = (const float*)d_in[3];   // [L, E, R, R]
    const float* bias = (const float*)d_in[4];   // [L, D]
    const float* gw   = (const float*)d_in[5];   // [E, D]
    float* out = (float*)d_out;

    float* p_xl = nullptr;
    cudaGetSymbolAddress((void**)&p_xl, g_xl);

    const int smem_gate = (4 * 4160 + 8 * 256) * (int)sizeof(float); // 74752 B
    cudaFuncSetAttribute(gate_mix, cudaFuncAttributeMaxDynamicSharedMemorySize, smem_gate);

    const int EB = Ee * Rr * Dd;   // 262144 per-layer stride for U and V

    dim3 g1(ER / BN, Bsz / BM);    // (2, 128)
    dim3 g2(Dd / BN, Bsz / BM);    // (8, 128)

    for (int l = 0; l < Ll; l++) {
        const float* xin  = (l == 0)      ? x   : p_xl;
        float*       xout = (l == Ll - 1) ? out : p_xl;
        gemm1_tanh   <<<g1, 256>>>(xin, V + (size_t)l * EB);
        gate_mix     <<<Bsz / 8, 256, smem_gate>>>(xin, C + (size_t)l * Ee * Rr * Rr, gw);
        gemm2_combine<<<g2, 256>>>(U + (size_t)l * EB, xin, x, bias + (size_t)l * Dd, xout);
    }
}